// round 17
// baseline (speedup 1.0000x reference)
#include <cuda_runtime.h>
#include <cuda_bf16.h>
#include <cstdint>

// Problem constants (fixed by the dataset)
#define MAXN 100000
#define MAXE 600000
#define DF   128            // feature dim (in == hid == 128)

// ---------------------------------------------------------------------------
// Scratch (no allocations allowed -> __device__ globals)
// ---------------------------------------------------------------------------
__device__ float g_y[(size_t)MAXN * DF];    // y = z_pre * dinv[row]  (GEMM output)
__device__ float g_agg[(size_t)MAXN * DF];  // S = y[i] + sum_{j->i} y[j]
__device__ int   g_deg[MAXN];
__device__ float g_dinv[MAXN];
// CSR (by destination node)
__device__ int   g_csr_src[MAXE];
__device__ int   g_off[MAXN + 1];
__device__ int   g_cur[MAXN];
__device__ int   g_bsum[128];
__device__ int   g_boff[128];
// W split into bf16 hi/lo, stored TRANSPOSED: g_Bhi[n*DF + k] = hi(W[k][n])
__device__ __nv_bfloat16 g_Bhi[DF * DF];
__device__ __nv_bfloat16 g_Blo[DF * DF];

// ---------------------------------------------------------------------------
// Degree / normalization
// ---------------------------------------------------------------------------
__global__ void deg_init_kernel(int n) {
    int i = blockIdx.x * blockDim.x + threadIdx.x;
    if (i < n) g_deg[i] = 1;   // self-loop
}

__global__ void deg_count_kernel(const int* __restrict__ dst, int E) {
    int e = blockIdx.x * blockDim.x + threadIdx.x;
    if (e < E) atomicAdd(&g_deg[dst[e]], 1);
}

__global__ void dinv_kernel(int n) {
    int i = blockIdx.x * blockDim.x + threadIdx.x;
    if (i < n) g_dinv[i] = rsqrtf((float)g_deg[i]);
}

// ---------------------------------------------------------------------------
// W split + transpose: g_Bhi[n*DF+k] = bf16_hi(W[k][n]), g_Blo = bf16 residual
// ---------------------------------------------------------------------------
__global__ void wsplit_kernel(const float* __restrict__ W) {
    int i = blockIdx.x * blockDim.x + threadIdx.x;   // 16384 elements
    if (i >= DF * DF) return;
    int k = i / DF, n = i % DF;
    float f = W[i];
    __nv_bfloat16 h = __float2bfloat16(f);
    float r = f - __bfloat162float(h);
    g_Bhi[n * DF + k] = h;
    g_Blo[n * DF + k] = __float2bfloat16(r);
}

// ---------------------------------------------------------------------------
// CSR build: exclusive scan of cnt[i] = deg[i]-1 (in-edge count), then bucket
// fill. 3-kernel exact scan (block scan -> scan of block sums -> add offsets).
// ---------------------------------------------------------------------------
static constexpr int SCAN_B  = 1024;

__global__ void scanA_kernel(int n) {
    __shared__ int sh[SCAN_B];
    int t = threadIdx.x, b = blockIdx.x;
    int i = b * SCAN_B + t;
    int v = (i < n) ? (g_deg[i] - 1) : 0;
    sh[t] = v;
    __syncthreads();
    #pragma unroll
    for (int o = 1; o < SCAN_B; o <<= 1) {
        int x = (t >= o) ? sh[t - o] : 0;
        __syncthreads();
        sh[t] += x;
        __syncthreads();
    }
    int incl = sh[t];
    if (i <= n) g_off[i] = incl - v;           // exclusive, pre-block-offset
    if (t == SCAN_B - 1) g_bsum[b] = incl;     // block total
}

__global__ void scanB_kernel(int nb) {
    __shared__ int sh[128];
    int t = threadIdx.x;
    sh[t] = (t < nb) ? g_bsum[t] : 0;
    __syncthreads();
    if (t == 0) {
        int run = 0;
        for (int b = 0; b < nb; b++) { int x = sh[b]; sh[b] = run; run += x; }
    }
    __syncthreads();
    if (t < nb) g_boff[t] = sh[t];
}

__global__ void scanC_kernel(int n) {
    int t = threadIdx.x, b = blockIdx.x;
    int i = b * SCAN_B + t;
    if (i <= n) {
        int o = g_off[i] + g_boff[b];
        g_off[i] = o;
        if (i < n) g_cur[i] = o;
    }
}

__global__ void csr_fill_kernel(const int* __restrict__ src,
                                const int* __restrict__ dst, int E) {
    int e = blockIdx.x * blockDim.x + threadIdx.x;
    if (e >= E) return;
    int s = src[e], d = dst[e];
    int pos = atomicAdd(&g_cur[d], 1);
    g_csr_src[pos] = s;
}

// ---------------------------------------------------------------------------
// PTX helpers (plain sm_80+ features only; this build rejects tcgen05)
// ---------------------------------------------------------------------------
__device__ __forceinline__ uint32_t smem_to_u32(const void* smem_ptr) {
    uint32_t addr;
    asm("{ .reg .u64 tmp; cvta.to.shared.u64 tmp, %1; cvt.u32.u64 %0, tmp; }"
        : "=r"(addr) : "l"(smem_ptr));
    return addr;
}

#define LDSM_X4(R0, R1, R2, R3, addr) \
    asm volatile("ldmatrix.sync.aligned.m8n8.x4.shared.b16 {%0,%1,%2,%3}, [%4];" \
                 : "=r"(R0), "=r"(R1), "=r"(R2), "=r"(R3) : "r"(addr))

__device__ __forceinline__ void mma_bf16(float* d, const uint32_t* a,
                                         uint32_t b0, uint32_t b1) {
    asm volatile(
        "mma.sync.aligned.m16n8k16.row.col.f32.bf16.bf16.f32 "
        "{%0,%1,%2,%3}, {%4,%5,%6,%7}, {%8,%9}, {%0,%1,%2,%3};"
        : "+f"(d[0]), "+f"(d[1]), "+f"(d[2]), "+f"(d[3])
        : "r"(a[0]), "r"(a[1]), "r"(a[2]), "r"(a[3]), "r"(b0), "r"(b1));
}

__device__ __forceinline__ uint32_t pack_bf2(__nv_bfloat16 a, __nv_bfloat16 b) {
    __nv_bfloat162 t;
    t.x = a; t.y = b;
    return *reinterpret_cast<uint32_t*>(&t);
}

// ---------------------------------------------------------------------------
// GEMM SMEM layout: BM=64 tile. Row stride padded to 272 B (128 bf16 + 16 B)
// -> consecutive rows start 4 banks apart; ldmatrix phases & 8B STS conflict-
// free (proven correct in the earlier mma variant).
// Ah/Al: 64 rows; Bh/Bl: 128 rows. Total 104448 B/CTA -> 2 CTAs/SM (227KB).
// ---------------------------------------------------------------------------
static constexpr int RSTRIDE   = 272;
static constexpr int OFF_AH    = 0;
static constexpr int OFF_AL    = 64 * RSTRIDE;            // 17408
static constexpr int OFF_BH    = 2 * 64 * RSTRIDE;        // 34816
static constexpr int OFF_BL    = OFF_BH + 128 * RSTRIDE;  // 69632
static constexpr int SMEM_GEMM = OFF_BL + 128 * RSTRIDE;  // 104448

// ---------------------------------------------------------------------------
// Tensor-core GEMM via mma.sync (bf16-split 3-term fp32 emulation):
//   y = act(A) @ W * dinv[row]
//   ASRC=0: A = Aext (x);  ASRC=1: A[i][k] = relu(g_agg[i][k]*dinv[i] + b[k])
// Terms: Ah@Bh + Ah@Bl + Al@Bh. 256 threads, BM=64, warp tile 16(M) x 64(N),
// warps: warp_m = wid&3, warp_n = wid>>2. Reads g_agg, writes g_y (no alias).
// ---------------------------------------------------------------------------
template<int ASRC, bool PRERELU>
__global__ void __launch_bounds__(256, 2)
gemm_mma_kernel(const float* __restrict__ Aext,
                const float* __restrict__ preBias,
                int M)
{
    extern __shared__ char smem[];
    const uint32_t sb = smem_to_u32(smem);
    const int tid  = threadIdx.x;
    const int wid  = tid >> 5;
    const int lane = tid & 31;
    const int rowBase = blockIdx.x * 64;

    const float* A = (ASRC == 0) ? Aext : g_agg;

    // ---- stage A: 64 rows; warp w handles rows w, w+8, ... (8 rows) ----
    float4 bb = make_float4(0.f, 0.f, 0.f, 0.f);
    if (PRERELU) bb = *(const float4*)(preBias + lane * 4);
    for (int r = wid; r < 64; r += 8) {
        int grow = rowBase + r;
        float4 v = make_float4(0.f, 0.f, 0.f, 0.f);
        if (grow < M) v = ((const float4*)(A + (size_t)grow * DF))[lane];
        if (PRERELU) {
            float di = g_dinv[grow < M ? grow : 0];
            v.x = fmaxf(fmaf(v.x, di, bb.x), 0.f);
            v.y = fmaxf(fmaf(v.y, di, bb.y), 0.f);
            v.z = fmaxf(fmaf(v.z, di, bb.z), 0.f);
            v.w = fmaxf(fmaf(v.w, di, bb.w), 0.f);
            if (grow >= M) { v.x = v.y = v.z = v.w = 0.f; }
        }
        __nv_bfloat16 hx = __float2bfloat16(v.x), hy = __float2bfloat16(v.y);
        __nv_bfloat16 hz = __float2bfloat16(v.z), hw = __float2bfloat16(v.w);
        __nv_bfloat16 lx = __float2bfloat16(v.x - __bfloat162float(hx));
        __nv_bfloat16 ly = __float2bfloat16(v.y - __bfloat162float(hy));
        __nv_bfloat16 lz = __float2bfloat16(v.z - __bfloat162float(hz));
        __nv_bfloat16 lw = __float2bfloat16(v.w - __bfloat162float(hw));
        uint32_t off = (uint32_t)(r * RSTRIDE + lane * 8);
        asm volatile("st.shared.v2.b32 [%0], {%1, %2};"
                     :: "r"(sb + OFF_AH + off),
                        "r"(pack_bf2(hx, hy)), "r"(pack_bf2(hz, hw)) : "memory");
        asm volatile("st.shared.v2.b32 [%0], {%1, %2};"
                     :: "r"(sb + OFF_AL + off),
                        "r"(pack_bf2(lx, ly)), "r"(pack_bf2(lz, lw)) : "memory");
    }

    // ---- stage B: W hi/lo, already [n][k] in global; 128 rows ----
    for (int n = wid; n < 128; n += 8) {
        uint2 hp = ((const uint2*)(g_Bhi + (size_t)n * DF))[lane];
        uint2 lp = ((const uint2*)(g_Blo + (size_t)n * DF))[lane];
        uint32_t off = (uint32_t)(n * RSTRIDE + lane * 8);
        asm volatile("st.shared.v2.b32 [%0], {%1, %2};"
                     :: "r"(sb + OFF_BH + off), "r"(hp.x), "r"(hp.y) : "memory");
        asm volatile("st.shared.v2.b32 [%0], {%1, %2};"
                     :: "r"(sb + OFF_BL + off), "r"(lp.x), "r"(lp.y) : "memory");
    }
    __syncthreads();

    // ---- warp tile 16(M) x 64(N) ----
    const int m0 = (wid & 3) * 16;
    const int n0 = (wid >> 2) * 64;

    float acc[8][4];
    #pragma unroll
    for (int j = 0; j < 8; j++)
        #pragma unroll
        for (int q = 0; q < 4; q++) acc[j][q] = 0.f;

    const int lrow = lane & 15;            // 16 rows
    const int lkof = (lane >> 4) * 16;     // k-half byte offset

    #pragma unroll
    for (int p = 0; p < 3; p++) {
        const uint32_t aBase = sb + ((p == 2) ? OFF_AL : OFF_AH);
        const uint32_t bBase = sb + ((p == 1) ? OFF_BL : OFF_BH);
        #pragma unroll
        for (int ks = 0; ks < 8; ks++) {
            const int kb = ks * 32;        // 16 bf16 = 32 bytes
            uint32_t a[4];
            {
                uint32_t addr = aBase + (uint32_t)((m0 + lrow) * RSTRIDE + kb + lkof);
                LDSM_X4(a[0], a[1], a[2], a[3], addr);
            }
            uint32_t b[4][4];
            #pragma unroll
            for (int j2 = 0; j2 < 4; j2++) {
                uint32_t addr = bBase + (uint32_t)((n0 + j2 * 16 + lrow) * RSTRIDE
                                                   + kb + lkof);
                LDSM_X4(b[j2][0], b[j2][1], b[j2][2], b[j2][3], addr);
            }
            #pragma unroll
            for (int j2 = 0; j2 < 4; j2++) {
                mma_bf16(acc[j2 * 2 + 0], a, b[j2][0], b[j2][2]);
                mma_bf16(acc[j2 * 2 + 1], a, b[j2][1], b[j2][3]);
            }
        }
    }

    // ---- epilogue: y = acc * dinv[row] ----
    #pragma unroll
    for (int h = 0; h < 2; h++) {          // h=0 -> rows +0..7, h=1 -> rows +8..15
        int grow = rowBase + m0 + h * 8 + (lane >> 2);
        if (grow >= M) continue;
        float di = g_dinv[grow];
        size_t base = (size_t)grow * DF + n0 + (lane & 3) * 2;
        #pragma unroll
        for (int j = 0; j < 8; j++) {
            float2 v = make_float2(acc[j][h * 2 + 0] * di, acc[j][h * 2 + 1] * di);
            *(float2*)(g_y + base + j * 8) = v;
        }
    }
}

// ---------------------------------------------------------------------------
// CSR gather aggregation: warp per node.
//   S[i] = y[i] + sum_{e in in(i)} y[src[e]]        (no atomics, streaming out)
// ---------------------------------------------------------------------------
__global__ void gather_kernel(int N)
{
    int node = (blockIdx.x * blockDim.x + threadIdx.x) >> 5;
    int lane = threadIdx.x & 31;
    if (node >= N) return;
    int beg = g_off[node];
    int end = g_off[node + 1];
    float4 acc = ((const float4*)(g_y + (size_t)node * DF))[lane];   // self term
    for (int e = beg; e < end; e++) {
        int s = g_csr_src[e];
        float4 v = ((const float4*)(g_y + (size_t)s * DF))[lane];
        acc.x += v.x; acc.y += v.y; acc.z += v.z; acc.w += v.w;
    }
    ((float4*)(g_agg + (size_t)node * DF))[lane] = acc;
}

// ---------------------------------------------------------------------------
// Edge decode: z2[i] = S2[i]*dinv[i] + b2;  out[e] = <z2[src], z2[dst]>
// ---------------------------------------------------------------------------
__global__ void edge_dot_kernel(const int* __restrict__ src,
                                const int* __restrict__ dst,
                                const float* __restrict__ bias,
                                float* __restrict__ out,
                                int E)
{
    int warp = (blockIdx.x * blockDim.x + threadIdx.x) >> 5;
    int lane = threadIdx.x & 31;
    if (warp >= E) return;
    int s = __ldg(src + warp);
    int d = __ldg(dst + warp);
    float ds = g_dinv[s];
    float dd = g_dinv[d];
    float4 bb = *(const float4*)(bias + lane * 4);
    float4 a  = *(const float4*)(g_agg + (size_t)s * DF + lane * 4);
    float4 b  = *(const float4*)(g_agg + (size_t)d * DF + lane * 4);
    float p = fmaf(a.x, ds, bb.x) * fmaf(b.x, dd, bb.x)
            + fmaf(a.y, ds, bb.y) * fmaf(b.y, dd, bb.y)
            + fmaf(a.z, ds, bb.z) * fmaf(b.z, dd, bb.z)
            + fmaf(a.w, ds, bb.w) * fmaf(b.w, dd, bb.w);
    #pragma unroll
    for (int o = 16; o > 0; o >>= 1)
        p += __shfl_xor_sync(0xffffffffu, p, o);
    if (lane == 0) out[warp] = p;
}

// ---------------------------------------------------------------------------
// kernel_launch
// Inputs (metadata order): x [N*128], edge_index [2*E], W1, b1, W2, b2
// ---------------------------------------------------------------------------
extern "C" void kernel_launch(void* const* d_in, const int* in_sizes, int n_in,
                              void* d_out, int out_size)
{
    const float* x  = (const float*)d_in[0];
    const int*   ei = (const int*)  d_in[1];
    const float* W1 = (const float*)d_in[2];
    const float* b1 = (const float*)d_in[3];
    const float* W2 = (const float*)d_in[4];
    const float* b2 = (const float*)d_in[5];

    int E = in_sizes[1] / 2;
    int N = in_sizes[0] / DF;
    if (N > MAXN) N = MAXN;
    if (E > MAXE) E = MAXE;

    const int* src = ei;
    const int* dst = ei + E;
    float* out = (float*)d_out;

    const int T = 256;
    int nb = (N + SCAN_B - 1) / SCAN_B;

    cudaFuncSetAttribute(gemm_mma_kernel<0, false>,
                         cudaFuncAttributeMaxDynamicSharedMemorySize, SMEM_GEMM);
    cudaFuncSetAttribute(gemm_mma_kernel<1, true>,
                         cudaFuncAttributeMaxDynamicSharedMemorySize, SMEM_GEMM);

    // ---- degrees, normalization, CSR build ----
    deg_init_kernel<<<(N + T - 1) / T, T>>>(N);
    deg_count_kernel<<<(E + T - 1) / T, T>>>(dst, E);
    dinv_kernel<<<(N + T - 1) / T, T>>>(N);
    scanA_kernel<<<nb, SCAN_B>>>(N);
    scanB_kernel<<<1, 128>>>(nb);
    scanC_kernel<<<nb, SCAN_B>>>(N);
    csr_fill_kernel<<<(E + T - 1) / T, T>>>(src, dst, E);

    int gemm_blocks = (N + 63) / 64;
    int node_blocks = (N + 7) / 8;   // warp per node, 8 warps/block
    int edge_blocks = (E + 7) / 8;   // warp per edge

    // ---- Layer 1: y1 = (x @ W1) * dinv ; S1 = gather(y1) ----
    wsplit_kernel<<<(DF * DF + T - 1) / T, T>>>(W1);
    gemm_mma_kernel<0, false><<<gemm_blocks, T, SMEM_GEMM>>>(x, nullptr, N);
    gather_kernel<<<node_blocks, T>>>(N);
    // g_agg = S1 (raw sums; dinv + b1 + relu applied in GEMM2's A-load)

    // ---- Layer 2: y2 = relu(S1*dinv + b1) @ W2 * dinv ; S2 = gather(y2) ----
    wsplit_kernel<<<(DF * DF + T - 1) / T, T>>>(W2);
    gemm_mma_kernel<1, true><<<gemm_blocks, T, SMEM_GEMM>>>(nullptr, b1, N);
    gather_kernel<<<node_blocks, T>>>(N);
    // g_agg = S2 (dinv + b2 applied in decode)

    // ---- Decode: per-edge dot of endpoint embeddings ----
    edge_dot_kernel<<<edge_blocks, T>>>(src, dst, b2, out, E);
}